// round 16
// baseline (speedup 1.0000x reference)
#include <cuda_runtime.h>
#include <cuda_fp16.h>
#include <math.h>
#include <stdint.h>

#define BATCH  64
#define CDIM   384
#define HIN    28
#define WIN    28
#define LQ     785
#define LKV    197
#define NHEADS 6
#define HDIM   64
#define EPSB   1e-5f
#define QSCALE 0.051031036307982884f

#define MQP   50304            // 393 * 128
#define MKVP  12672            // 99 * 128
#define QTILES  393
#define KVTILES 99
#define MTILES  (QTILES + 2 * KVTILES)   // 591

// ---------------- device scratch (half precision operands) ----------------
__device__ __align__(16) __half g_qc[MQP  * CDIM];
__device__ __align__(16) __half g_kc[MKVP * CDIM];
__device__ __align__(16) __half g_vc[MKVP * CDIM];
__device__ __align__(16) __half g_Q [MQP  * CDIM];
__device__ __align__(16) __half g_K [MKVP * CDIM];
__device__ __align__(16) __half g_V [MKVP * CDIM];
__device__ __align__(16) __half g_WT[3 * CDIM * CDIM];   // W transposed: [n][k]

// ---------------- helpers ----------------
__device__ __forceinline__ uint32_t smem_u32(const void* p) {
    uint32_t a;
    asm("{ .reg .u64 t; cvta.to.shared.u64 t, %1; cvt.u32.u64 %0, t; }" : "=r"(a) : "l"(p));
    return a;
}
__device__ __forceinline__ void cp16(uint32_t s, const void* g) {
    asm volatile("cp.async.cg.shared.global [%0], [%1], 16;" :: "r"(s), "l"(g) : "memory");
}
__device__ __forceinline__ void cp16z(uint32_t s, const void* g, int srcsize) {
    asm volatile("cp.async.cg.shared.global [%0], [%1], 16, %2;"
                 :: "r"(s), "l"(g), "r"(srcsize) : "memory");
}
#define CP_COMMIT() asm volatile("cp.async.commit_group;" ::: "memory")
template <int N>
__device__ __forceinline__ void cp_wait() {
    asm volatile("cp.async.wait_group %0;" :: "n"(N) : "memory");
}
__device__ __forceinline__ uint32_t h2pack(float x, float y) {
    __half2 h = __floats2half2_rn(x, y);
    return *(uint32_t*)&h;
}

#define LDSM_X4(r0, r1, r2, r3, addr) \
    asm volatile("ldmatrix.sync.aligned.m8n8.x4.shared.b16 {%0,%1,%2,%3}, [%4];" \
                 : "=r"(r0), "=r"(r1), "=r"(r2), "=r"(r3) : "r"(addr))
#define LDSM_X1(r0, addr) \
    asm volatile("ldmatrix.sync.aligned.m8n8.x1.shared.b16 {%0}, [%1];" \
                 : "=r"(r0) : "r"(addr))

// D += A(16x16,row) * B(16x8,col)   fp16 in, fp32 acc
__device__ __forceinline__ void mma16(float* d, const uint32_t* a, const uint32_t* b) {
    asm volatile(
        "mma.sync.aligned.m16n8k16.row.col.f32.f16.f16.f32 "
        "{%0,%1,%2,%3}, {%4,%5,%6,%7}, {%8,%9}, {%0,%1,%2,%3};"
        : "+f"(d[0]), "+f"(d[1]), "+f"(d[2]), "+f"(d[3])
        : "r"(a[0]), "r"(a[1]), "r"(a[2]), "r"(a[3]), "r"(b[0]), "r"(b[1]));
}
// D += A(16x8,row) * B(8x8,col)   fp16 k8 tail
__device__ __forceinline__ void mma8h(float* d, const uint32_t* a, uint32_t b) {
    asm volatile(
        "mma.sync.aligned.m16n8k8.row.col.f32.f16.f16.f32 "
        "{%0,%1,%2,%3}, {%4,%5}, {%6}, {%0,%1,%2,%3};"
        : "+f"(d[0]), "+f"(d[1]), "+f"(d[2]), "+f"(d[3])
        : "r"(a[0]), "r"(a[1]), "r"(b));
}

// ---------------- fused depthwise convs + BN + cls copy (unchanged) ----------------
__global__ __launch_bounds__(CDIM) void conv_fused_kernel(
    const float* __restrict__ hs,
    const float* __restrict__ wq, const float* __restrict__ gq,
    const float* __restrict__ beq, const float* __restrict__ mq,
    const float* __restrict__ vq,
    const float* __restrict__ wk, const float* __restrict__ gk,
    const float* __restrict__ bek, const float* __restrict__ mk,
    const float* __restrict__ vk,
    const float* __restrict__ wv, const float* __restrict__ gv,
    const float* __restrict__ bev, const float* __restrict__ mv,
    const float* __restrict__ vvv) {
    int c = threadIdx.x;
    int i = blockIdx.x % 14;
    int b = blockIdx.x / 14;
    const float* xb = hs + (size_t)b * LQ * CDIM + CDIM;

    if (i == 0) {
        __half v = __float2half_rn(hs[(size_t)b * LQ * CDIM + c]);
        g_qc[(size_t)b * LQ  * CDIM + c] = v;
        g_kc[(size_t)b * LKV * CDIM + c] = v;
        g_vc[(size_t)b * LKV * CDIM + c] = v;
    }

    float fq[9], fk[9], fv[9];
#pragma unroll
    for (int j = 0; j < 9; j++) {
        fq[j] = wq[j * CDIM + c];
        fk[j] = wk[j * CDIM + c];
        fv[j] = wv[j * CDIM + c];
    }
    float sq  = gq[c] * rsqrtf(vq[c]  + EPSB);
    float shq = beq[c] - mq[c] * sq;
    float sk  = gk[c] * rsqrtf(vk[c]  + EPSB);
    float shk = bek[c] - mk[c] * sk;
    float sv  = gv[c] * rsqrtf(vvv[c] + EPSB);
    float shv = bev[c] - mv[c] * sv;

    bool v0 = (i > 0), v3 = (i < 13);
    const float* r0 = xb + (size_t)(2 * i - 1) * WIN * CDIM + c;
    const float* r1 = xb + (size_t)(2 * i)     * WIN * CDIM + c;
    const float* r2 = xb + (size_t)(2 * i + 1) * WIN * CDIM + c;
    const float* r3 = xb + (size_t)(2 * i + 2) * WIN * CDIM + c;

    __half* oqA = g_qc + (size_t)b * LQ  * CDIM + (size_t)(1 + (2 * i)     * WIN) * CDIM + c;
    __half* oqB = g_qc + (size_t)b * LQ  * CDIM + (size_t)(1 + (2 * i + 1) * WIN) * CDIM + c;
    size_t okv = (size_t)b * LKV * CDIM + (size_t)(1 + i * 14) * CDIM + c;
    __half* ok = g_kc + okv;
    __half* ov = g_vc + okv;

    float xp[4], xc[4], xn[4];
#pragma unroll
    for (int r = 0; r < 4; r++) xp[r] = 0.f;
    xc[0] = v0 ? r0[0] : 0.f;
    xc[1] = r1[0];
    xc[2] = r2[0];
    xc[3] = v3 ? r3[0] : 0.f;

#pragma unroll
    for (int ow = 0; ow < WIN; ow++) {
        if (ow < WIN - 1) {
            size_t o = (size_t)(ow + 1) * CDIM;
            xn[0] = v0 ? r0[o] : 0.f;
            xn[1] = r1[o];
            xn[2] = r2[o];
            xn[3] = v3 ? r3[o] : 0.f;
        } else {
            xn[0] = xn[1] = xn[2] = xn[3] = 0.f;
        }
        float aq = xp[0] * fq[0];
        aq = fmaf(xc[0], fq[1], aq); aq = fmaf(xn[0], fq[2], aq);
        aq = fmaf(xp[1], fq[3], aq); aq = fmaf(xc[1], fq[4], aq);
        aq = fmaf(xn[1], fq[5], aq); aq = fmaf(xp[2], fq[6], aq);
        aq = fmaf(xc[2], fq[7], aq); aq = fmaf(xn[2], fq[8], aq);
        oqA[(size_t)ow * CDIM] = __float2half_rn(aq * sq + shq);
        float ab = xp[1] * fq[0];
        ab = fmaf(xc[1], fq[1], ab); ab = fmaf(xn[1], fq[2], ab);
        ab = fmaf(xp[2], fq[3], ab); ab = fmaf(xc[2], fq[4], ab);
        ab = fmaf(xn[2], fq[5], ab); ab = fmaf(xp[3], fq[6], ab);
        ab = fmaf(xc[3], fq[7], ab); ab = fmaf(xn[3], fq[8], ab);
        oqB[(size_t)ow * CDIM] = __float2half_rn(ab * sq + shq);
        if ((ow & 1) == 0) {
            float ak = xp[0] * fk[0];
            ak = fmaf(xc[0], fk[1], ak); ak = fmaf(xn[0], fk[2], ak);
            ak = fmaf(xp[1], fk[3], ak); ak = fmaf(xc[1], fk[4], ak);
            ak = fmaf(xn[1], fk[5], ak); ak = fmaf(xp[2], fk[6], ak);
            ak = fmaf(xc[2], fk[7], ak); ak = fmaf(xn[2], fk[8], ak);
            float av = xp[0] * fv[0];
            av = fmaf(xc[0], fv[1], av); av = fmaf(xn[0], fv[2], av);
            av = fmaf(xp[1], fv[3], av); av = fmaf(xc[1], fv[4], av);
            av = fmaf(xn[1], fv[5], av); av = fmaf(xp[2], fv[6], av);
            av = fmaf(xc[2], fv[7], av); av = fmaf(xn[2], fv[8], av);
            ok[(size_t)(ow >> 1) * CDIM] = __float2half_rn(ak * sk + shk);
            ov[(size_t)(ow >> 1) * CDIM] = __float2half_rn(av * sv + shv);
        }
#pragma unroll
        for (int r = 0; r < 4; r++) { xp[r] = xc[r]; xc[r] = xn[r]; }
    }
}

// ---------------- W transpose: g_WT[n][k] = half(W[k][n]) ----------------
__global__ void transpose_w_kernel(const float* __restrict__ Wq,
                                   const float* __restrict__ Wk,
                                   const float* __restrict__ Wv) {
    __shared__ float t[32][33];
    int z = blockIdx.z;
    const float* src = (z == 0) ? Wq : (z == 1) ? Wk : Wv;
    __half* dst = g_WT + (size_t)z * CDIM * CDIM;
    int tx = threadIdx.x, ty = threadIdx.y;
    int x = blockIdx.x * 32 + tx;
    int y0 = blockIdx.y * 32;
#pragma unroll
    for (int r = 0; r < 32; r += 8)
        t[ty + r][tx] = src[(size_t)(y0 + ty + r) * CDIM + x];
    __syncthreads();
    int n = blockIdx.x * 32 + ty;
#pragma unroll
    for (int r = 0; r < 32; r += 8)
        dst[(size_t)(n + r) * CDIM + y0 + tx] = __float2half_rn(t[tx][ty + r]);
}

// ---------------- fp16 mma GEMM, 3-stage cp.async pipeline, single sync/stage ----------------
#define APH     72
#define STAGE_H (2 * 128 * APH)
#define GEMM_SMEM (3 * STAGE_H * 2)    // 110,592 B

__global__ __launch_bounds__(256, 2) void gemm_mma_kernel(
    const float* __restrict__ bq, const float* __restrict__ bk,
    const float* __restrict__ bv) {
    extern __shared__ __half gsh[];

    int mt = blockIdx.y, ntile = blockIdx.x;
    int sel, mloc;
    if (mt < QTILES)                 { sel = 0; mloc = mt; }
    else if (mt < QTILES + KVTILES)  { sel = 1; mloc = mt - QTILES; }
    else                             { sel = 2; mloc = mt - QTILES - KVTILES; }
    const __half* A    = (sel == 0) ? g_qc : (sel == 1) ? g_kc : g_vc;
    __half*       C    = (sel == 0) ? g_Q  : (sel == 1) ? g_K  : g_V;
    const __half* WT   = g_WT + (size_t)sel * CDIM * CDIM;
    const float*  bias = (sel == 0) ? bq : (sel == 1) ? bk : bv;
    const float oscale = (sel == 0) ? QSCALE : 1.0f;
    const int m0 = mloc * 128, n0 = ntile * 128;

    const int tid = threadIdx.x, lane = tid & 31, wid = tid >> 5;
    const int gid = lane >> 2, tig = lane & 3;
    const int wm = wid & 3, wn = wid >> 2;

    const int crow = tid >> 3;
    const int cseg = (tid & 7) * 8;
    const __half* Ag = A  + ((size_t)(m0 + crow)) * CDIM + cseg;
    const __half* Bg = WT + ((size_t)(n0 + crow)) * CDIM + cseg;
    uint32_t sbase = smem_u32(gsh);

    const int lrow = lane & 7;
    const uint32_t a_lm = (uint32_t)(((((lane >> 3) & 1) * 8 + lrow) * APH + ((lane >> 4) * 8)) * 2);
    const uint32_t b_lm = (uint32_t)((((lane >> 4) * 8 + lrow) * APH + (((lane >> 3) & 1) * 8)) * 2);

    float acc[2][8][4];
#pragma unroll
    for (int i = 0; i < 2; i++)
#pragma unroll
        for (int j = 0; j < 8; j++)
#pragma unroll
            for (int c = 0; c < 4; c++) acc[i][j][c] = 0.f;

#define G_ISSUE(s)                                                               \
    do {                                                                         \
        int st_ = (s) % 3;                                                       \
        int k0_ = (s) * 64;                                                      \
        uint32_t as_ = sbase + (uint32_t)(st_ * STAGE_H) * 2u;                   \
        uint32_t bs_ = as_ + (uint32_t)(128 * APH) * 2u;                         \
        _Pragma("unroll")                                                        \
        for (int i_ = 0; i_ < 4; i_++) {                                         \
            cp16(as_ + (uint32_t)(((crow + 32 * i_) * APH + cseg) * 2),          \
                 Ag + (size_t)(32 * i_) * CDIM + k0_);                           \
            cp16(bs_ + (uint32_t)(((crow + 32 * i_) * APH + cseg) * 2),          \
                 Bg + (size_t)(32 * i_) * CDIM + k0_);                           \
        }                                                                        \
    } while (0)

    G_ISSUE(0); CP_COMMIT();
    G_ISSUE(1); CP_COMMIT();

#pragma unroll 1
    for (int s = 0; s < 6; s++) {
        if (s < 5) cp_wait<1>();
        else       cp_wait<0>();
        __syncthreads();
        if (s + 2 < 6) { G_ISSUE(s + 2); CP_COMMIT(); }

        uint32_t ab_ = sbase + (uint32_t)((s % 3) * STAGE_H) * 2u;
        uint32_t bb_ = ab_ + (uint32_t)(128 * APH) * 2u;
        uint32_t aw_ = ab_ + (uint32_t)(wm * 32 * APH * 2) + a_lm;
        uint32_t bw_ = bb_ + (uint32_t)(wn * 64 * APH * 2) + b_lm;
#pragma unroll
        for (int kk = 0; kk < 4; kk++) {
            uint32_t kof = (uint32_t)(kk * 16 * 2);
            uint32_t a[2][4];
            LDSM_X4(a[0][0], a[0][1], a[0][2], a[0][3], aw_ + kof);
            LDSM_X4(a[1][0], a[1][1], a[1][2], a[1][3], aw_ + (uint32_t)(16 * APH * 2) + kof);
#pragma unroll
            for (int np = 0; np < 4; np++) {
                uint32_t b0, b1, b2, b3;
                LDSM_X4(b0, b1, b2, b3, bw_ + (uint32_t)(np * 16 * APH * 2) + kof);
                uint32_t bbA[2] = { b0, b1 };
                uint32_t bbB[2] = { b2, b3 };
                mma16(acc[0][2 * np],     a[0], bbA);
                mma16(acc[1][2 * np],     a[1], bbA);
                mma16(acc[0][2 * np + 1], a[0], bbB);
                mma16(acc[1][2 * np + 1], a[1], bbB);
            }
        }
    }
#undef G_ISSUE

#pragma unroll
    for (int m2 = 0; m2 < 2; m2++) {
        int row = m0 + wm * 32 + m2 * 16 + gid;
#pragma unroll
        for (int nt = 0; nt < 8; nt++) {
            int col = n0 + wn * 64 + nt * 8 + 2 * tig;
            float b0 = bias[col], b1 = bias[col + 1];
            uint32_t p0 = h2pack((acc[m2][nt][0] + b0) * oscale,
                                 (acc[m2][nt][1] + b1) * oscale);
            uint32_t p1 = h2pack((acc[m2][nt][2] + b0) * oscale,
                                 (acc[m2][nt][3] + b1) * oscale);
            *(uint32_t*)(C + (size_t)row * CDIM + col)       = p0;
            *(uint32_t*)(C + (size_t)(row + 8) * CDIM + col) = p1;
        }
    }
}

// ---------------- fp16 attention (R14) with 2-way CTA split per (b,h) ----------------
// grid = BATCH*NHEADS*2; each half stages K/V and handles tiles vw, vw+16, ...
// where vw = half*8 + wid. Cuts the wave tail: 2 waves x 7 tiles -> 3 waves x 4 tiles.
#define NKV2  200
#define KPH   72
#define VPH   200
#define QPH   72
#define NTIL  50
#define NWARP 8
#define VWSTRIDE 16
#define ATTN_SMEM ((NKV2 * KPH + HDIM * VPH + NWARP * 2 * 16 * QPH) * 2)   // 91,264 B

__global__ __launch_bounds__(256, 2) void attn_mma_kernel(float* __restrict__ out) {
    extern __shared__ __half smh[];
    __half* Ks  = smh;                          // [200][72]
    __half* VsT = smh + NKV2 * KPH;             // [64][200]
    __half* Qs  = VsT + HDIM * VPH;             // [8][2][16][72]

    int bh   = blockIdx.x >> 1;
    int half = blockIdx.x & 1;
    int b = bh / NHEADS, h = bh % NHEADS;
    int tid = threadIdx.x, lane = tid & 31, wid = tid >> 5;
    int gid = lane >> 2, tig = lane & 3;
    const int vw = half * NWARP + wid;          // virtual warp 0..15

    const __half* Kg = g_K + ((size_t)b * LKV) * CDIM + h * HDIM;
    const __half* Vg = g_V + ((size_t)b * LKV) * CDIM + h * HDIM;
    const __half* Qg = g_Q + ((size_t)b * LQ)  * CDIM + h * HDIM;

    const uint32_t qs_base = smem_u32(Qs) + (uint32_t)(wid * 2 * 16 * QPH * 2);

#define Q_PRE(it_, buf_)                                                        \
    do {                                                                        \
        int t0_ = (it_) * 16;                                                   \
        uint32_t dst_ = qs_base + (uint32_t)((buf_) * 16 * QPH * 2);            \
        _Pragma("unroll")                                                       \
        for (int j_ = 0; j_ < 4; j_++) {                                        \
            int op_ = lane * 4 + j_;                                            \
            int r_ = op_ >> 3, sg_ = (op_ & 7) * 8;                             \
            int t_ = t0_ + r_;                                                  \
            cp16z(dst_ + (uint32_t)((r_ * QPH + sg_) * 2),                      \
                  Qg + (size_t)t_ * CDIM + sg_, (t_ < LQ) ? 16 : 0);            \
        }                                                                       \
    } while (0)

    Q_PRE(vw, 0);
    CP_COMMIT();

    for (int i = tid; i < NKV2 * 8; i += 256) {
        int n = i >> 3, seg = (i & 7) * 8;
        uint4 kv = make_uint4(0, 0, 0, 0), vv = kv;
        if (n < LKV) {
            kv = *(const uint4*)(Kg + (size_t)n * CDIM + seg);
            vv = *(const uint4*)(Vg + (size_t)n * CDIM + seg);
        }
        *(uint4*)&Ks[n * KPH + seg] = kv;
        const __half* vh = (const __half*)&vv;
#pragma unroll
        for (int j = 0; j < 8; j++)
            VsT[(seg + j) * VPH + n] = vh[j];
    }
    __syncthreads();

    const int lrow = lane & 7, lmat = lane >> 3;
    const uint32_t ks_lm = smem_u32(Ks)  + (uint32_t)((lrow * KPH + lmat * 8) * 2);
    const uint32_t vs_lm = smem_u32(VsT) + (uint32_t)((lrow * VPH + lmat * 8) * 2);
    const uint32_t vs_t  = smem_u32(VsT) + (uint32_t)((lrow * VPH + 192) * 2);
    const uint32_t qa_lm = (uint32_t)(((((lane >> 3) & 1) * 8 + lrow) * QPH + ((lane >> 4) * 8)) * 2);

    const bool mL0 = (192 + 2 * tig < LKV);
    const bool mL1 = (193 + 2 * tig < LKV);

    int qbuf = 0;
#pragma unroll 1
    for (int it = vw; it < NTIL; it += VWSTRIDE) {
        const int t0 = it * 16;
        const int tA = t0 + gid, tB = tA + 8;
        const bool vA = tA < LQ, vB = tB < LQ;
        const int buf = qbuf;
        qbuf ^= 1;

        cp_wait<0>();
        __syncwarp();
        if (it + VWSTRIDE < NTIL) {
            Q_PRE(it + VWSTRIDE, buf ^ 1);
            CP_COMMIT();
        }

        uint32_t qa[4][4];
        {
            uint32_t qb = qs_base + (uint32_t)(buf * 16 * QPH * 2) + qa_lm;
#pragma unroll
            for (int kc = 0; kc < 4; kc++)
                LDSM_X4(qa[kc][0], qa[kc][1], qa[kc][2], qa[kc][3],
                        qb + (uint32_t)(kc * 16 * 2));
        }

        float acc2[8][4];
#pragma unroll
        for (int nt = 0; nt < 8; nt++)
#pragma unroll
            for (int c = 0; c < 4; c++) acc2[nt][c] = 0.f;
        float l0 = 0.f, l1 = 0.f;

#pragma unroll
        for (int ch = 0; ch < 6; ch++) {
            float sc[4][4];
#pragma unroll
            for (int j = 0; j < 4; j++)
#pragma unroll
                for (int c = 0; c < 4; c++) sc[j][c] = 0.f;

#pragma unroll
            for (int j = 0; j < 4; j++) {
                uint32_t base = ks_lm + (uint32_t)((4 * ch + j) * 8 * KPH * 2);
                uint32_t b0, b1, b2, b3, b4, b5, b6, b7;
                LDSM_X4(b0, b1, b2, b3, base);
                LDSM_X4(b4, b5, b6, b7, base + 64);
                uint32_t p0[2] = { b0, b1 }, p1[2] = { b2, b3 };
                uint32_t p2[2] = { b4, b5 }, p3[2] = { b6, b7 };
                mma16(sc[j], qa[0], p0);
                mma16(sc[j], qa[1], p1);
                mma16(sc[j], qa[2], p2);
                mma16(sc[j], qa[3], p3);
            }

            uint32_t pA[4], pB[4];
#pragma unroll
            for (int j = 0; j < 4; j++) {
                float e0 = __expf(sc[j][0]);
                float e1 = __expf(sc[j][1]);
                float e2 = __expf(sc[j][2]);
                float e3 = __expf(sc[j][3]);
                l0 += e0 + e1;
                l1 += e2 + e3;
                pA[j] = h2pack(e0, e1);
                pB[j] = h2pack(e2, e3);
            }

            uint32_t aF[4] = { pA[0], pB[0], pA[1], pB[1] };
            uint32_t aS[4] = { pA[2], pB[2], pA[3], pB[3] };
            uint32_t kof = (uint32_t)(ch * 64);
#pragma unroll
            for (int nt = 0; nt < 8; nt++) {
                uint32_t b0, b1, b2, b3;
                LDSM_X4(b0, b1, b2, b3, vs_lm + (uint32_t)(nt * 8 * VPH * 2) + kof);
                uint32_t bbF[2] = { b0, b1 };
                uint32_t bbS[2] = { b2, b3 };
                mma16(acc2[nt], aF, bbF);
                mma16(acc2[nt], aS, bbS);
            }
        }

        {
            float sc[4];
#pragma unroll
            for (int c = 0; c < 4; c++) sc[c] = 0.f;
            uint32_t base = ks_lm + (uint32_t)(24 * 8 * KPH * 2);
            uint32_t b0, b1, b2, b3, b4, b5, b6, b7;
            LDSM_X4(b0, b1, b2, b3, base);
            LDSM_X4(b4, b5, b6, b7, base + 64);
            uint32_t p0[2] = { b0, b1 }, p1[2] = { b2, b3 };
            uint32_t p2[2] = { b4, b5 }, p3[2] = { b6, b7 };
            mma16(sc, qa[0], p0);
            mma16(sc, qa[1], p1);
            mma16(sc, qa[2], p2);
            mma16(sc, qa[3], p3);

            float e0 = mL0 ? __expf(sc[0]) : 0.f;
            float e1 = mL1 ? __expf(sc[1]) : 0.f;
            float e2 = mL0 ? __expf(sc[2]) : 0.f;
            float e3 = mL1 ? __expf(sc[3]) : 0.f;
            l0 += e0 + e1;
            l1 += e2 + e3;
            uint32_t a8[2] = { h2pack(e0, e1), h2pack(e2, e3) };
#pragma unroll
            for (int nt = 0; nt < 8; nt++) {
                uint32_t bt;
                LDSM_X1(bt, vs_t + (uint32_t)(nt * 8 * VPH * 2));
                mma8h(acc2[nt], a8, bt);
            }
        }

        l0 += __shfl_xor_sync(0xffffffffu, l0, 1);
        l0 += __shfl_xor_sync(0xffffffffu, l0, 2);
        l1 += __shfl_xor_sync(0xffffffffu, l1, 1);
        l1 += __shfl_xor_sync(0xffffffffu, l1, 2);
        float inv0 = 1.f / l0, inv1 = 1.f / l1;

#pragma unroll
        for (int nt = 0; nt < 8; nt++) {
            int col = h * HDIM + nt * 8 + 2 * tig;
            if (vA) {
                float2 v = { acc2[nt][0] * inv0, acc2[nt][1] * inv0 };
                *(float2*)(out + ((size_t)b * LQ + tA) * CDIM + col) = v;
            }
            if (vB) {
                float2 v = { acc2[nt][2] * inv1, acc2[nt][3] * inv1 };
                *(float2*)(out + ((size_t)b * LQ + tB) * CDIM + col) = v;
            }
        }
    }
#undef Q_PRE
}

// ---------------- entry point ----------------
extern "C" void kernel_launch(void* const* d_in, const int* in_sizes, int n_in,
                              void* d_out, int out_size) {
    (void)in_sizes; (void)n_in; (void)out_size;
    const float* hs   = (const float*)d_in[0];
    const float* wdwq = (const float*)d_in[3];
    const float* gq   = (const float*)d_in[4];
    const float* beq  = (const float*)d_in[5];
    const float* mq   = (const float*)d_in[6];
    const float* vq   = (const float*)d_in[7];
    const float* Wq   = (const float*)d_in[8];
    const float* bq   = (const float*)d_in[9];
    const float* wdwk = (const float*)d_in[10];
    const float* gk   = (const float*)d_in[11];
    const float* bek  = (const float*)d_in[12];
    const float* mk   = (const float*)d_in[13];
    const float* vk   = (const float*)d_in[14];
    const float* Wk   = (const float*)d_in[15];
    const float* bk   = (const float*)d_in[16];
    const float* wdwv = (const float*)d_in[17];
    const float* gv   = (const float*)d_in[18];
    const float* bev  = (const float*)d_in[19];
    const float* mv   = (const float*)d_in[20];
    const float* vv   = (const float*)d_in[21];
    const float* Wv   = (const float*)d_in[22];
    const float* bv   = (const float*)d_in[23];
    float* out = (float*)d_out;

    cudaFuncSetAttribute(gemm_mma_kernel,
                         cudaFuncAttributeMaxDynamicSharedMemorySize, GEMM_SMEM);
    cudaFuncSetAttribute(attn_mma_kernel,
                         cudaFuncAttributeMaxDynamicSharedMemorySize, ATTN_SMEM);

    conv_fused_kernel<<<BATCH * 14, CDIM>>>(hs,
                                            wdwq, gq, beq, mq, vq,
                                            wdwk, gk, bek, mk, vk,
                                            wdwv, gv, bev, mv, vv);
    transpose_w_kernel<<<dim3(12, 12, 3), dim3(32, 8)>>>(Wq, Wk, Wv);
    gemm_mma_kernel<<<dim3(3, MTILES), 256, GEMM_SMEM>>>(bq, bk, bv);
    attn_mma_kernel<<<BATCH * NHEADS * 2, 256, ATTN_SMEM>>>(out);
}

// round 17
// speedup vs baseline: 1.0284x; 1.0284x over previous
#include <cuda_runtime.h>
#include <cuda_fp16.h>
#include <math.h>
#include <stdint.h>

#define BATCH  64
#define CDIM   384
#define HIN    28
#define WIN    28
#define LQ     785
#define LKV    197
#define NHEADS 6
#define HDIM   64
#define EPSB   1e-5f
#define QSCALE 0.051031036307982884f

#define MQP   50304            // 393 * 128
#define MKVP  12672            // 99 * 128
#define QTILES  393
#define KVTILES 99
#define MTILES  (QTILES + 2 * KVTILES)   // 591

// ---------------- device scratch (half precision operands) ----------------
__device__ __align__(16) __half g_qc[MQP  * CDIM];
__device__ __align__(16) __half g_kc[MKVP * CDIM];
__device__ __align__(16) __half g_vc[MKVP * CDIM];
__device__ __align__(16) __half g_Q [MQP  * CDIM];
__device__ __align__(16) __half g_K [MKVP * CDIM];
__device__ __align__(16) __half g_V [MKVP * CDIM];
__device__ __align__(16) __half g_WT[3 * CDIM * CDIM];   // W transposed: [n][k]

// ---------------- helpers ----------------
__device__ __forceinline__ uint32_t smem_u32(const void* p) {
    uint32_t a;
    asm("{ .reg .u64 t; cvta.to.shared.u64 t, %1; cvt.u32.u64 %0, t; }" : "=r"(a) : "l"(p));
    return a;
}
__device__ __forceinline__ void cp16(uint32_t s, const void* g) {
    asm volatile("cp.async.cg.shared.global [%0], [%1], 16;" :: "r"(s), "l"(g) : "memory");
}
__device__ __forceinline__ void cp16z(uint32_t s, const void* g, int srcsize) {
    asm volatile("cp.async.cg.shared.global [%0], [%1], 16, %2;"
                 :: "r"(s), "l"(g), "r"(srcsize) : "memory");
}
#define CP_COMMIT() asm volatile("cp.async.commit_group;" ::: "memory")
template <int N>
__device__ __forceinline__ void cp_wait() {
    asm volatile("cp.async.wait_group %0;" :: "n"(N) : "memory");
}
__device__ __forceinline__ uint32_t h2pack(float x, float y) {
    __half2 h = __floats2half2_rn(x, y);
    return *(uint32_t*)&h;
}

#define LDSM_X4(r0, r1, r2, r3, addr) \
    asm volatile("ldmatrix.sync.aligned.m8n8.x4.shared.b16 {%0,%1,%2,%3}, [%4];" \
                 : "=r"(r0), "=r"(r1), "=r"(r2), "=r"(r3) : "r"(addr))
#define LDSM_X4T(r0, r1, r2, r3, addr) \
    asm volatile("ldmatrix.sync.aligned.m8n8.x4.trans.shared.b16 {%0,%1,%2,%3}, [%4];" \
                 : "=r"(r0), "=r"(r1), "=r"(r2), "=r"(r3) : "r"(addr))
#define LDSM_X1T(r0, addr) \
    asm volatile("ldmatrix.sync.aligned.m8n8.x1.trans.shared.b16 {%0}, [%1];" \
                 : "=r"(r0) : "r"(addr))

// D += A(16x16,row) * B(16x8,col)   fp16 in, fp32 acc
__device__ __forceinline__ void mma16(float* d, const uint32_t* a, const uint32_t* b) {
    asm volatile(
        "mma.sync.aligned.m16n8k16.row.col.f32.f16.f16.f32 "
        "{%0,%1,%2,%3}, {%4,%5,%6,%7}, {%8,%9}, {%0,%1,%2,%3};"
        : "+f"(d[0]), "+f"(d[1]), "+f"(d[2]), "+f"(d[3])
        : "r"(a[0]), "r"(a[1]), "r"(a[2]), "r"(a[3]), "r"(b[0]), "r"(b[1]));
}
// D += A(16x8,row) * B(8x8,col)   fp16 k8 tail
__device__ __forceinline__ void mma8h(float* d, const uint32_t* a, uint32_t b) {
    asm volatile(
        "mma.sync.aligned.m16n8k8.row.col.f32.f16.f16.f32 "
        "{%0,%1,%2,%3}, {%4,%5}, {%6}, {%0,%1,%2,%3};"
        : "+f"(d[0]), "+f"(d[1]), "+f"(d[2]), "+f"(d[3])
        : "r"(a[0]), "r"(a[1]), "r"(b));
}

// ---------------- fused depthwise convs + BN + cls copy (unchanged) ----------------
__global__ __launch_bounds__(CDIM) void conv_fused_kernel(
    const float* __restrict__ hs,
    const float* __restrict__ wq, const float* __restrict__ gq,
    const float* __restrict__ beq, const float* __restrict__ mq,
    const float* __restrict__ vq,
    const float* __restrict__ wk, const float* __restrict__ gk,
    const float* __restrict__ bek, const float* __restrict__ mk,
    const float* __restrict__ vk,
    const float* __restrict__ wv, const float* __restrict__ gv,
    const float* __restrict__ bev, const float* __restrict__ mv,
    const float* __restrict__ vvv) {
    int c = threadIdx.x;
    int i = blockIdx.x % 14;
    int b = blockIdx.x / 14;
    const float* xb = hs + (size_t)b * LQ * CDIM + CDIM;

    if (i == 0) {
        __half v = __float2half_rn(hs[(size_t)b * LQ * CDIM + c]);
        g_qc[(size_t)b * LQ  * CDIM + c] = v;
        g_kc[(size_t)b * LKV * CDIM + c] = v;
        g_vc[(size_t)b * LKV * CDIM + c] = v;
    }

    float fq[9], fk[9], fv[9];
#pragma unroll
    for (int j = 0; j < 9; j++) {
        fq[j] = wq[j * CDIM + c];
        fk[j] = wk[j * CDIM + c];
        fv[j] = wv[j * CDIM + c];
    }
    float sq  = gq[c] * rsqrtf(vq[c]  + EPSB);
    float shq = beq[c] - mq[c] * sq;
    float sk  = gk[c] * rsqrtf(vk[c]  + EPSB);
    float shk = bek[c] - mk[c] * sk;
    float sv  = gv[c] * rsqrtf(vvv[c] + EPSB);
    float shv = bev[c] - mv[c] * sv;

    bool v0 = (i > 0), v3 = (i < 13);
    const float* r0 = xb + (size_t)(2 * i - 1) * WIN * CDIM + c;
    const float* r1 = xb + (size_t)(2 * i)     * WIN * CDIM + c;
    const float* r2 = xb + (size_t)(2 * i + 1) * WIN * CDIM + c;
    const float* r3 = xb + (size_t)(2 * i + 2) * WIN * CDIM + c;

    __half* oqA = g_qc + (size_t)b * LQ  * CDIM + (size_t)(1 + (2 * i)     * WIN) * CDIM + c;
    __half* oqB = g_qc + (size_t)b * LQ  * CDIM + (size_t)(1 + (2 * i + 1) * WIN) * CDIM + c;
    size_t okv = (size_t)b * LKV * CDIM + (size_t)(1 + i * 14) * CDIM + c;
    __half* ok = g_kc + okv;
    __half* ov = g_vc + okv;

    float xp[4], xc[4], xn[4];
#pragma unroll
    for (int r = 0; r < 4; r++) xp[r] = 0.f;
    xc[0] = v0 ? r0[0] : 0.f;
    xc[1] = r1[0];
    xc[2] = r2[0];
    xc[3] = v3 ? r3[0] : 0.f;

#pragma unroll
    for (int ow = 0; ow < WIN; ow++) {
        if (ow < WIN - 1) {
            size_t o = (size_t)(ow + 1) * CDIM;
            xn[0] = v0 ? r0[o] : 0.f;
            xn[1] = r1[o];
            xn[2] = r2[o];
            xn[3] = v3 ? r3[o] : 0.f;
        } else {
            xn[0] = xn[1] = xn[2] = xn[3] = 0.f;
        }
        float aq = xp[0] * fq[0];
        aq = fmaf(xc[0], fq[1], aq); aq = fmaf(xn[0], fq[2], aq);
        aq = fmaf(xp[1], fq[3], aq); aq = fmaf(xc[1], fq[4], aq);
        aq = fmaf(xn[1], fq[5], aq); aq = fmaf(xp[2], fq[6], aq);
        aq = fmaf(xc[2], fq[7], aq); aq = fmaf(xn[2], fq[8], aq);
        oqA[(size_t)ow * CDIM] = __float2half_rn(aq * sq + shq);
        float ab = xp[1] * fq[0];
        ab = fmaf(xc[1], fq[1], ab); ab = fmaf(xn[1], fq[2], ab);
        ab = fmaf(xp[2], fq[3], ab); ab = fmaf(xc[2], fq[4], ab);
        ab = fmaf(xn[2], fq[5], ab); ab = fmaf(xp[3], fq[6], ab);
        ab = fmaf(xc[3], fq[7], ab); ab = fmaf(xn[3], fq[8], ab);
        oqB[(size_t)ow * CDIM] = __float2half_rn(ab * sq + shq);
        if ((ow & 1) == 0) {
            float ak = xp[0] * fk[0];
            ak = fmaf(xc[0], fk[1], ak); ak = fmaf(xn[0], fk[2], ak);
            ak = fmaf(xp[1], fk[3], ak); ak = fmaf(xc[1], fk[4], ak);
            ak = fmaf(xn[1], fk[5], ak); ak = fmaf(xp[2], fk[6], ak);
            ak = fmaf(xc[2], fk[7], ak); ak = fmaf(xn[2], fk[8], ak);
            float av = xp[0] * fv[0];
            av = fmaf(xc[0], fv[1], av); av = fmaf(xn[0], fv[2], av);
            av = fmaf(xp[1], fv[3], av); av = fmaf(xc[1], fv[4], av);
            av = fmaf(xn[1], fv[5], av); av = fmaf(xp[2], fv[6], av);
            av = fmaf(xc[2], fv[7], av); av = fmaf(xn[2], fv[8], av);
            ok[(size_t)(ow >> 1) * CDIM] = __float2half_rn(ak * sk + shk);
            ov[(size_t)(ow >> 1) * CDIM] = __float2half_rn(av * sv + shv);
        }
#pragma unroll
        for (int r = 0; r < 4; r++) { xp[r] = xc[r]; xc[r] = xn[r]; }
    }
}

// ---------------- W transpose: g_WT[n][k] = half(W[k][n]) ----------------
__global__ void transpose_w_kernel(const float* __restrict__ Wq,
                                   const float* __restrict__ Wk,
                                   const float* __restrict__ Wv) {
    __shared__ float t[32][33];
    int z = blockIdx.z;
    const float* src = (z == 0) ? Wq : (z == 1) ? Wk : Wv;
    __half* dst = g_WT + (size_t)z * CDIM * CDIM;
    int tx = threadIdx.x, ty = threadIdx.y;
    int x = blockIdx.x * 32 + tx;
    int y0 = blockIdx.y * 32;
#pragma unroll
    for (int r = 0; r < 32; r += 8)
        t[ty + r][tx] = src[(size_t)(y0 + ty + r) * CDIM + x];
    __syncthreads();
    int n = blockIdx.x * 32 + ty;
#pragma unroll
    for (int r = 0; r < 32; r += 8)
        dst[(size_t)(n + r) * CDIM + y0 + tx] = __float2half_rn(t[tx][ty + r]);
}

// ---------------- fp16 mma GEMM, 3-stage cp.async pipeline, single sync/stage ----------------
#define APH     72
#define STAGE_H (2 * 128 * APH)
#define GEMM_SMEM (3 * STAGE_H * 2)    // 110,592 B

__global__ __launch_bounds__(256, 2) void gemm_mma_kernel(
    const float* __restrict__ bq, const float* __restrict__ bk,
    const float* __restrict__ bv) {
    extern __shared__ __half gsh[];

    int mt = blockIdx.y, ntile = blockIdx.x;
    int sel, mloc;
    if (mt < QTILES)                 { sel = 0; mloc = mt; }
    else if (mt < QTILES + KVTILES)  { sel = 1; mloc = mt - QTILES; }
    else                             { sel = 2; mloc = mt - QTILES - KVTILES; }
    const __half* A    = (sel == 0) ? g_qc : (sel == 1) ? g_kc : g_vc;
    __half*       C    = (sel == 0) ? g_Q  : (sel == 1) ? g_K  : g_V;
    const __half* WT   = g_WT + (size_t)sel * CDIM * CDIM;
    const float*  bias = (sel == 0) ? bq : (sel == 1) ? bk : bv;
    const float oscale = (sel == 0) ? QSCALE : 1.0f;
    const int m0 = mloc * 128, n0 = ntile * 128;

    const int tid = threadIdx.x, lane = tid & 31, wid = tid >> 5;
    const int gid = lane >> 2, tig = lane & 3;
    const int wm = wid & 3, wn = wid >> 2;

    const int crow = tid >> 3;
    const int cseg = (tid & 7) * 8;
    const __half* Ag = A  + ((size_t)(m0 + crow)) * CDIM + cseg;
    const __half* Bg = WT + ((size_t)(n0 + crow)) * CDIM + cseg;
    uint32_t sbase = smem_u32(gsh);

    const int lrow = lane & 7;
    const uint32_t a_lm = (uint32_t)(((((lane >> 3) & 1) * 8 + lrow) * APH + ((lane >> 4) * 8)) * 2);
    const uint32_t b_lm = (uint32_t)((((lane >> 4) * 8 + lrow) * APH + (((lane >> 3) & 1) * 8)) * 2);

    float acc[2][8][4];
#pragma unroll
    for (int i = 0; i < 2; i++)
#pragma unroll
        for (int j = 0; j < 8; j++)
#pragma unroll
            for (int c = 0; c < 4; c++) acc[i][j][c] = 0.f;

#define G_ISSUE(s)                                                               \
    do {                                                                         \
        int st_ = (s) % 3;                                                       \
        int k0_ = (s) * 64;                                                      \
        uint32_t as_ = sbase + (uint32_t)(st_ * STAGE_H) * 2u;                   \
        uint32_t bs_ = as_ + (uint32_t)(128 * APH) * 2u;                         \
        _Pragma("unroll")                                                        \
        for (int i_ = 0; i_ < 4; i_++) {                                         \
            cp16(as_ + (uint32_t)(((crow + 32 * i_) * APH + cseg) * 2),          \
                 Ag + (size_t)(32 * i_) * CDIM + k0_);                           \
            cp16(bs_ + (uint32_t)(((crow + 32 * i_) * APH + cseg) * 2),          \
                 Bg + (size_t)(32 * i_) * CDIM + k0_);                           \
        }                                                                        \
    } while (0)

    G_ISSUE(0); CP_COMMIT();
    G_ISSUE(1); CP_COMMIT();

#pragma unroll 1
    for (int s = 0; s < 6; s++) {
        if (s < 5) cp_wait<1>();
        else       cp_wait<0>();
        __syncthreads();
        if (s + 2 < 6) { G_ISSUE(s + 2); CP_COMMIT(); }

        uint32_t ab_ = sbase + (uint32_t)((s % 3) * STAGE_H) * 2u;
        uint32_t bb_ = ab_ + (uint32_t)(128 * APH) * 2u;
        uint32_t aw_ = ab_ + (uint32_t)(wm * 32 * APH * 2) + a_lm;
        uint32_t bw_ = bb_ + (uint32_t)(wn * 64 * APH * 2) + b_lm;
#pragma unroll
        for (int kk = 0; kk < 4; kk++) {
            uint32_t kof = (uint32_t)(kk * 16 * 2);
            uint32_t a[2][4];
            LDSM_X4(a[0][0], a[0][1], a[0][2], a[0][3], aw_ + kof);
            LDSM_X4(a[1][0], a[1][1], a[1][2], a[1][3], aw_ + (uint32_t)(16 * APH * 2) + kof);
#pragma unroll
            for (int np = 0; np < 4; np++) {
                uint32_t b0, b1, b2, b3;
                LDSM_X4(b0, b1, b2, b3, bw_ + (uint32_t)(np * 16 * APH * 2) + kof);
                uint32_t bbA[2] = { b0, b1 };
                uint32_t bbB[2] = { b2, b3 };
                mma16(acc[0][2 * np],     a[0], bbA);
                mma16(acc[1][2 * np],     a[1], bbA);
                mma16(acc[0][2 * np + 1], a[0], bbB);
                mma16(acc[1][2 * np + 1], a[1], bbB);
            }
        }
    }
#undef G_ISSUE

#pragma unroll
    for (int m2 = 0; m2 < 2; m2++) {
        int row = m0 + wm * 32 + m2 * 16 + gid;
#pragma unroll
        for (int nt = 0; nt < 8; nt++) {
            int col = n0 + wn * 64 + nt * 8 + 2 * tig;
            float b0 = bias[col], b1 = bias[col + 1];
            uint32_t p0 = h2pack((acc[m2][nt][0] + b0) * oscale,
                                 (acc[m2][nt][1] + b1) * oscale);
            uint32_t p1 = h2pack((acc[m2][nt][2] + b0) * oscale,
                                 (acc[m2][nt][3] + b1) * oscale);
            *(uint32_t*)(C + (size_t)row * CDIM + col)       = p0;
            *(uint32_t*)(C + (size_t)(row + 8) * CDIM + col) = p1;
        }
    }
}

// ---------------- fp16 attention (R15 scheduling) + V row-major + ldmatrix.trans ----------------
// V stored row-major [200][72] (vectorized, conflict-free staging like K);
// PV b-frags via ldmatrix.x4.trans (row stride 144B -> conflict-free).
#define NKV2  200
#define KPH   72
#define VPH2  72
#define QPH   72
#define NTIL  50
#define NWARP 8
// smem: Ks[200][72] + Vs[200][72] + Qs[8][2][16][72]
#define ATTN_SMEM ((NKV2 * KPH + NKV2 * VPH2 + NWARP * 2 * 16 * QPH) * 2)   // 94,464 B

__global__ __launch_bounds__(256, 2) void attn_mma_kernel(float* __restrict__ out) {
    extern __shared__ __half smh[];
    __half* Ks = smh;                           // [200][72]
    __half* Vs = smh + NKV2 * KPH;              // [200][72] row-major
    __half* Qs = Vs + NKV2 * VPH2;              // [8][2][16][72]

    int bh = blockIdx.x;
    int b = bh / NHEADS, h = bh % NHEADS;
    int tid = threadIdx.x, lane = tid & 31, wid = tid >> 5;
    int gid = lane >> 2, tig = lane & 3;

    const __half* Kg = g_K + ((size_t)b * LKV) * CDIM + h * HDIM;
    const __half* Vg = g_V + ((size_t)b * LKV) * CDIM + h * HDIM;
    const __half* Qg = g_Q + ((size_t)b * LQ)  * CDIM + h * HDIM;

    const uint32_t qs_base = smem_u32(Qs) + (uint32_t)(wid * 2 * 16 * QPH * 2);

#define Q_PRE(it_, buf_)                                                        \
    do {                                                                        \
        int t0_ = (it_) * 16;                                                   \
        uint32_t dst_ = qs_base + (uint32_t)((buf_) * 16 * QPH * 2);            \
        _Pragma("unroll")                                                       \
        for (int j_ = 0; j_ < 4; j_++) {                                        \
            int op_ = lane * 4 + j_;                                            \
            int r_ = op_ >> 3, sg_ = (op_ & 7) * 8;                             \
            int t_ = t0_ + r_;                                                  \
            cp16z(dst_ + (uint32_t)((r_ * QPH + sg_) * 2),                      \
                  Qg + (size_t)t_ * CDIM + sg_, (t_ < LQ) ? 16 : 0);            \
        }                                                                       \
    } while (0)

    Q_PRE(wid, 0);
    CP_COMMIT();

    // stage K and V row-major, fully vectorized (no transpose stores)
    for (int i = tid; i < NKV2 * 8; i += 256) {
        int n = i >> 3, seg = (i & 7) * 8;
        uint4 kv = make_uint4(0, 0, 0, 0), vv = kv;
        if (n < LKV) {
            kv = *(const uint4*)(Kg + (size_t)n * CDIM + seg);
            vv = *(const uint4*)(Vg + (size_t)n * CDIM + seg);
        }
        *(uint4*)&Ks[n * KPH + seg] = kv;
        *(uint4*)&Vs[n * VPH2 + seg] = vv;
    }
    __syncthreads();

    const int lrow = lane & 7, lmat = lane >> 3;
    const uint32_t ks_lm = smem_u32(Ks) + (uint32_t)((lrow * KPH + lmat * 8) * 2);
    // V trans ldmatrix lane offset: row = (lane>>3 & 1)*8 + lrow (kv), col block = (lane>>4)*8 (dim)
    const uint32_t vt_lm = smem_u32(Vs) +
        (uint32_t)(((((lane >> 3) & 1) * 8 + lrow) * VPH2 + (lane >> 4) * 8) * 2);
    // tail x1 trans: rows 192+lrow
    const uint32_t vt_t  = smem_u32(Vs) + (uint32_t)(((192 + lrow) * VPH2) * 2);
    const uint32_t qa_lm = (uint32_t)(((((lane >> 3) & 1) * 8 + lrow) * QPH + ((lane >> 4) * 8)) * 2);

    const bool mL0 = (192 + 2 * tig < LKV);
    const bool mL1 = (193 + 2 * tig < LKV);

#pragma unroll 1
    for (int it = wid; it < NTIL; it += NWARP) {
        const int t0 = it * 16;
        const int tA = t0 + gid, tB = tA + 8;
        const bool vA = tA < LQ, vB = tB < LQ;
        const int buf = (it >> 3) & 1;

        cp_wait<0>();
        __syncwarp();
        if (it + NWARP < NTIL) {
            Q_PRE(it + NWARP, buf ^ 1);
            CP_COMMIT();
        }

        uint32_t qa[4][4];
        {
            uint32_t qb = qs_base + (uint32_t)(buf * 16 * QPH * 2) + qa_lm;
#pragma unroll
            for (int kc = 0; kc < 4; kc++)
                LDSM_X4(qa[kc][0], qa[kc][1], qa[kc][2], qa[kc][3],
                        qb + (uint32_t)(kc * 16 * 2));
        }

        float acc2[8][4];
#pragma unroll
        for (int nt = 0; nt < 8; nt++)
#pragma unroll
            for (int c = 0; c < 4; c++) acc2[nt][c] = 0.f;
        float l0 = 0.f, l1 = 0.f;

#pragma unroll
        for (int ch = 0; ch < 6; ch++) {
            float sc[4][4];
#pragma unroll
            for (int j = 0; j < 4; j++)
#pragma unroll
                for (int c = 0; c < 4; c++) sc[j][c] = 0.f;

#pragma unroll
            for (int j = 0; j < 4; j++) {
                uint32_t base = ks_lm + (uint32_t)((4 * ch + j) * 8 * KPH * 2);
                uint32_t b0, b1, b2, b3, b4, b5, b6, b7;
                LDSM_X4(b0, b1, b2, b3, base);
                LDSM_X4(b4, b5, b6, b7, base + 64);
                uint32_t p0[2] = { b0, b1 }, p1[2] = { b2, b3 };
                uint32_t p2[2] = { b4, b5 }, p3[2] = { b6, b7 };
                mma16(sc[j], qa[0], p0);
                mma16(sc[j], qa[1], p1);
                mma16(sc[j], qa[2], p2);
                mma16(sc[j], qa[3], p3);
            }

            uint32_t pA[4], pB[4];
#pragma unroll
            for (int j = 0; j < 4; j++) {
                float e0 = __expf(sc[j][0]);
                float e1 = __expf(sc[j][1]);
                float e2 = __expf(sc[j][2]);
                float e3 = __expf(sc[j][3]);
                l0 += e0 + e1;
                l1 += e2 + e3;
                pA[j] = h2pack(e0, e1);
                pB[j] = h2pack(e2, e3);
            }

            uint32_t aF[4] = { pA[0], pB[0], pA[1], pB[1] };
            uint32_t aS[4] = { pA[2], pB[2], pA[3], pB[3] };
            // PV: per nt-pair p, two x4.trans loads (k halves of the 32-kv chunk)
            uint32_t kb0 = (uint32_t)((ch * 32) * VPH2 * 2);
            uint32_t kb1 = kb0 + (uint32_t)(16 * VPH2 * 2);
#pragma unroll
            for (int p = 0; p < 4; p++) {
                uint32_t pof = (uint32_t)(p * 16 * 2);
                uint32_t b0, b1, b2, b3;
                LDSM_X4T(b0, b1, b2, b3, vt_lm + kb0 + pof);
                uint32_t bbF0[2] = { b0, b1 };
                uint32_t bbF1[2] = { b2, b3 };
                mma16(acc2[2 * p],     aF, bbF0);
                mma16(acc2[2 * p + 1], aF, bbF1);
                uint32_t c0, c1, c2, c3;
                LDSM_X4T(c0, c1, c2, c3, vt_lm + kb1 + pof);
                uint32_t bbS0[2] = { c0, c1 };
                uint32_t bbS1[2] = { c2, c3 };
                mma16(acc2[2 * p],     aS, bbS0);
                mma16(acc2[2 * p + 1], aS, bbS1);
            }
        }

        {
            float sc[4];
#pragma unroll
            for (int c = 0; c < 4; c++) sc[c] = 0.f;
            uint32_t base = ks_lm + (uint32_t)(24 * 8 * KPH * 2);
            uint32_t b0, b1, b2, b3, b4, b5, b6, b7;
            LDSM_X4(b0, b1, b2, b3, base);
            LDSM_X4(b4, b5, b6, b7, base + 64);
            uint32_t p0[2] = { b0, b1 }, p1[2] = { b2, b3 };
            uint32_t p2[2] = { b4, b5 }, p3[2] = { b6, b7 };
            mma16(sc, qa[0], p0);
            mma16(sc, qa[1], p1);
            mma16(sc, qa[2], p2);
            mma16(sc, qa[3], p3);

            float e0 = mL0 ? __expf(sc[0]) : 0.f;
            float e1 = mL1 ? __expf(sc[1]) : 0.f;
            float e2 = mL0 ? __expf(sc[2]) : 0.f;
            float e3 = mL1 ? __expf(sc[3]) : 0.f;
            l0 += e0 + e1;
            l1 += e2 + e3;
            uint32_t a8[2] = { h2pack(e0, e1), h2pack(e2, e3) };
#pragma unroll
            for (int nt = 0; nt < 8; nt++) {
                uint32_t bt;
                LDSM_X1T(bt, vt_t + (uint32_t)(nt * 8 * 2));
                mma8h(acc2[nt], a8, bt);
            }
        }

        l0 += __shfl_xor_sync(0xffffffffu, l0, 1);
        l0 += __shfl_xor_sync(0xffffffffu, l0, 2);
        l1 += __shfl_xor_sync(0xffffffffu, l1, 1);
        l1 += __shfl_xor_sync(0xffffffffu, l1, 2);
        float inv0 = 1.f / l0, inv1 = 1.f / l1;

#pragma unroll
        for (int nt = 0; nt < 8; nt++) {
            int col = h * HDIM + nt * 8 + 2 * tig;
            if (vA) {
                float2 v = { acc2[nt][0] * inv0, acc2[nt][1] * inv0 };
                *(float2*)(out + ((size_t)b * LQ + tA) * CDIM + col) = v;
            }
            if (vB) {
                float2 v = { acc2[nt][2] * inv1, acc2[nt][3] * inv1 };
                *(float2*)(out + ((size_t)b * LQ + tB) * CDIM + col) = v;
            }
        }
    }
#undef Q_PRE
}

// ---------------- entry point ----------------
extern "C" void kernel_launch(void* const* d_in, const int* in_sizes, int n_in,
                              void* d_out, int out_size) {
    (void)in_sizes; (void)n_in; (void)out_size;
    const float* hs   = (const float*)d_in[0];
    const float* wdwq = (const float*)d_in[3];
    const float* gq   = (const float*)d_in[4];
    const float* beq  = (const float*)d_in[5];
    const float* mq   = (const float*)d_in[6];
    const float* vq   = (const float*)d_in[7];
    const float* Wq   = (const float*)d_in[8];
    const float* bq   = (const float*)d_in[9];
    const float* wdwk = (const float*)d_in[10];
    const float* gk   = (const float*)d_in[11];
    const float* bek  = (const float*)d_in[12];
    const float* mk   = (const float*)d_in[13];
    const float* vk   = (const float*)d_in[14];
    const float* Wk   = (const float*)d_in[15];
    const float* bk   = (const float*)d_in[16];
    const float* wdwv = (const float*)d_in[17];
    const float* gv   = (const float*)d_in[18];
    const float* bev  = (const float*)d_in[19];
    const float* mv   = (const float*)d_in[20];
    const float* vv   = (const float*)d_in[21];
    const float* Wv   = (const float*)d_in[22];
    const float* bv   = (const float*)d_in[23];
    float* out = (float*)d_out;

    cudaFuncSetAttribute(gemm_mma_kernel,
                         cudaFuncAttributeMaxDynamicSharedMemorySize, GEMM_SMEM);
    cudaFuncSetAttribute(attn_mma_kernel,
                         cudaFuncAttributeMaxDynamicSharedMemorySize, ATTN_SMEM);

    conv_fused_kernel<<<BATCH * 14, CDIM>>>(hs,
                                            wdwq, gq, beq, mq, vq,
                                            wdwk, gk, bek, mk, vk,
                                            wdwv, gv, bev, mv, vv);
    transpose_w_kernel<<<dim3(12, 12, 3), dim3(32, 8)>>>(Wq, Wk, Wv);
    gemm_mma_kernel<<<dim3(3, MTILES), 256, GEMM_SMEM>>>(bq, bk, bv);
    attn_mma_kernel<<<BATCH * NHEADS, 256, ATTN_SMEM>>>(out);
}